// round 1
// baseline (speedup 1.0000x reference)
#include <cuda_runtime.h>
#include <cstdint>

#define SEQ   512
#define BATCH 256
#define CIN   64
#define HID   128
#define GATES 512   // 4*HID

// -------- scratch (static __device__ arrays; no allocation) --------
__device__ float g_xT[(size_t)SEQ * BATCH * CIN];     //  33 MB: x transposed to (S,B,C)
__device__ float g_xg[(size_t)SEQ * BATCH * GATES];   // 256 MB: pre-activations (S,B,4H)
__device__ float g_y1[(size_t)SEQ * BATCH * HID];     //  67 MB: layer-0 outputs (S,B,H)

typedef unsigned long long ull;

// -------- small helpers --------
__device__ __forceinline__ float fast_ex2(float x) {
    float y; asm("ex2.approx.f32 %0, %1;" : "=f"(y) : "f"(x)); return y;
}
__device__ __forceinline__ float fast_rcp(float x) {
    float y; asm("rcp.approx.f32 %0, %1;" : "=f"(y) : "f"(x)); return y;
}
__device__ __forceinline__ float sigmoid_f(float x) {
    // 1/(1+2^(-x*log2e)); saturates cleanly at both ends (rcp(inf)=0)
    float e = fast_ex2(-1.4426950408889634f * x);
    return fast_rcp(1.0f + e);
}
__device__ __forceinline__ float tanh_f(float x) {
    float ax = fabsf(x);
    float e  = fast_ex2(-2.8853900817779268f * ax);   // e^(-2|x|) in (0,1]
    float r  = fast_rcp(1.0f + e);
    float t  = fmaf(-2.0f * e, r, 1.0f);              // (1-e)/(1+e)
    return (x < 0.0f) ? -t : t;
}
__device__ __forceinline__ void ffma2(ull& acc, ull a, ull b) {
    asm("fma.rn.f32x2 %0, %1, %2, %0;" : "+l"(acc) : "l"(a), "l"(b));
}
__device__ __forceinline__ ull pack2(float lo, float hi) {
    ull r; asm("mov.b64 %0, {%1, %2};" : "=l"(r) : "f"(lo), "f"(hi)); return r;
}
__device__ __forceinline__ ull packr2(uint32_t lo, uint32_t hi) {
    ull r; asm("mov.b64 %0, {%1, %2};" : "=l"(r) : "r"(lo), "r"(hi)); return r;
}
__device__ __forceinline__ void unpack2(ull v, float& lo, float& hi) {
    asm("mov.b64 {%0, %1}, %2;" : "=f"(lo), "=f"(hi) : "l"(v));
}

// -------- kernel 1: transpose x (B,S,C) -> (S,B,C) --------
__global__ void k_transpose(const float* __restrict__ x) {
    int t = blockIdx.x * blockDim.x + threadIdx.x;   // enumerates (s,b,c), c fastest
    int c = t & (CIN - 1);
    int sb = t >> 6;
    int b = sb & (BATCH - 1);
    int s = sb >> 8;
    g_xT[t] = x[((size_t)b * SEQ + s) * CIN + c];
}

// -------- kernel 2/4: xg = A @ W^T + b1 + b2  (fp32, f32x2 accumulation) --------
// A: (M=S*B, K), W: (512, K), out: g_xg (M, 512)
// tiles: BM=128, BN=64, BK=16; 256 threads; per-thread 8(m)x4(n) with m-pairs packed.
template <int K, int ASEL>
__global__ __launch_bounds__(256) void k_gemm(const float* __restrict__ W,
                                              const float* __restrict__ b1,
                                              const float* __restrict__ b2) {
    const float* __restrict__ A = ASEL ? g_y1 : g_xT;

    __shared__ __align__(16) float As[16][128];
    __shared__ __align__(16) float Bs[16][64];

    const int tid   = threadIdx.x;
    const int mBase = blockIdx.x * 128;
    const int nBase = blockIdx.y * 64;

    const int aK = tid & 3;        // k-quad for loads
    const int aM = tid >> 2;       // 0..63
    const int ty = tid >> 4;       // 0..15 -> m0 = ty*8
    const int tx = tid & 15;       // 0..15 -> n0 = tx*4
    const int m0 = ty * 8;
    const int n0 = tx * 4;

    ull acc[4][4];
#pragma unroll
    for (int i = 0; i < 4; i++)
#pragma unroll
        for (int j = 0; j < 4; j++) acc[i][j] = 0ULL;

    for (int kt = 0; kt < K; kt += 16) {
        // load A tile (128 x 16), store transposed As[k][m]
#pragma unroll
        for (int p = 0; p < 2; p++) {
            int row = aM + p * 64;
            float4 v = *reinterpret_cast<const float4*>(
                &A[((size_t)(mBase + row)) * K + kt + aK * 4]);
            As[aK * 4 + 0][row] = v.x;
            As[aK * 4 + 1][row] = v.y;
            As[aK * 4 + 2][row] = v.z;
            As[aK * 4 + 3][row] = v.w;
        }
        // load W tile (64 x 16), store transposed Bs[k][n]
        {
            float4 v = *reinterpret_cast<const float4*>(
                &W[((size_t)(nBase + aM)) * K + kt + aK * 4]);
            Bs[aK * 4 + 0][aM] = v.x;
            Bs[aK * 4 + 1][aM] = v.y;
            Bs[aK * 4 + 2][aM] = v.z;
            Bs[aK * 4 + 3][aM] = v.w;
        }
        __syncthreads();

#pragma unroll
        for (int kk = 0; kk < 16; kk++) {
            const ulonglong2* ap = reinterpret_cast<const ulonglong2*>(&As[kk][m0]);
            ulonglong2 a01 = ap[0];
            ulonglong2 a23 = ap[1];
            float4 b4 = *reinterpret_cast<const float4*>(&Bs[kk][n0]);
            ull bp0 = pack2(b4.x, b4.x);
            ull bp1 = pack2(b4.y, b4.y);
            ull bp2 = pack2(b4.z, b4.z);
            ull bp3 = pack2(b4.w, b4.w);
            ffma2(acc[0][0], a01.x, bp0); ffma2(acc[0][1], a01.x, bp1);
            ffma2(acc[0][2], a01.x, bp2); ffma2(acc[0][3], a01.x, bp3);
            ffma2(acc[1][0], a01.y, bp0); ffma2(acc[1][1], a01.y, bp1);
            ffma2(acc[1][2], a01.y, bp2); ffma2(acc[1][3], a01.y, bp3);
            ffma2(acc[2][0], a23.x, bp0); ffma2(acc[2][1], a23.x, bp1);
            ffma2(acc[2][2], a23.x, bp2); ffma2(acc[2][3], a23.x, bp3);
            ffma2(acc[3][0], a23.y, bp0); ffma2(acc[3][1], a23.y, bp1);
            ffma2(acc[3][2], a23.y, bp2); ffma2(acc[3][3], a23.y, bp3);
        }
        __syncthreads();
    }

    // epilogue: + biases, write fp32 (float4 per m-row)
    float bs[4];
#pragma unroll
    for (int j = 0; j < 4; j++) {
        int n = nBase + n0 + j;
        bs[j] = b1[n] + b2[n];
    }
#pragma unroll
    for (int i = 0; i < 4; i++) {
        float lo[4], hi[4];
#pragma unroll
        for (int j = 0; j < 4; j++) unpack2(acc[i][j], lo[j], hi[j]);
        size_t r0 = ((size_t)(mBase + m0 + 2 * i)) * GATES + nBase + n0;
        float4 v0 = make_float4(lo[0] + bs[0], lo[1] + bs[1], lo[2] + bs[2], lo[3] + bs[3]);
        float4 v1 = make_float4(hi[0] + bs[0], hi[1] + bs[1], hi[2] + bs[2], hi[3] + bs[3]);
        *reinterpret_cast<float4*>(&g_xg[r0])         = v0;
        *reinterpret_cast<float4*>(&g_xg[r0 + GATES]) = v1;
    }
}

// -------- kernel 3/5: LSTM recurrence --------
// 128 CTAs x 512 threads; CTA owns 2 batch rows for all 512 steps.
// Thread j = gate column j. Whh row j held in registers as 64 bf16x2 words;
// expanded to f32 pairs per use (LOP3/SHF), fp32 f32x2 accumulation.
__global__ __launch_bounds__(512) void k_recur(const float* __restrict__ Whh,
                                               float* __restrict__ out, int layer) {
    __shared__ __align__(16) float sh[2][HID];    // current h (fp32)
    __shared__ __align__(16) float sg[2][GATES];  // activated gates

    const int j  = threadIdx.x;
    const int b0 = blockIdx.x * 2;

    // load + quantize my weight row to bf16x2 (64 regs)
    uint32_t wq[64];
    {
        const float2* wrow = reinterpret_cast<const float2*>(Whh + (size_t)j * HID);
#pragma unroll
        for (int k2 = 0; k2 < 64; k2++) {
            float2 v = wrow[k2];
            uint32_t w;
            asm("cvt.rn.bf16x2.f32 %0, %1, %2;" : "=r"(w) : "f"(v.y), "f"(v.x)); // lo=v.x
            wq[k2] = w;
        }
    }

    // init state
    if (j < 256) sh[j >> 7][j & (HID - 1)] = 0.0f;
    float c = 0.0f;
    __syncthreads();

    const int gt = j >> 7;  // 0:i 1:f 2:g 3:o

    for (int t = 0; t < SEQ; t++) {
        // pre-activations from the hoisted input GEMM (streamed from DRAM;
        // independent loads -> scheduled early, latency hidden by the dot)
        size_t base = ((size_t)t * BATCH + b0) * GATES + j;
        float xg0 = g_xg[base];
        float xg1 = g_xg[base + GATES];

        // dot(h_row, Whh_row_j) for both batch rows, fp32 f32x2 accumulation
        ull acc0 = 0ULL, acc1 = 0ULL;
        const ulonglong2* h0p = reinterpret_cast<const ulonglong2*>(sh[0]);
        const ulonglong2* h1p = reinterpret_cast<const ulonglong2*>(sh[1]);
#pragma unroll
        for (int g = 0; g < 32; g++) {   // 4 h-values per iteration
            ulonglong2 hv0 = h0p[g];
            ulonglong2 hv1 = h1p[g];
            uint32_t wa_ = wq[2 * g], wb_ = wq[2 * g + 1];
            ull wa = packr2(wa_ << 16, wa_ & 0xFFFF0000u);
            ull wb = packr2(wb_ << 16, wb_ & 0xFFFF0000u);
            ffma2(acc0, wa, hv0.x);
            ffma2(acc0, wb, hv0.y);
            ffma2(acc1, wa, hv1.x);
            ffma2(acc1, wb, hv1.y);
        }
        float l0, h0, l1, h1;
        unpack2(acc0, l0, h0);
        unpack2(acc1, l1, h1);
        float p0 = xg0 + l0 + h0;
        float p1 = xg1 + l1 + h1;

        float a0 = (gt == 2) ? tanh_f(p0) : sigmoid_f(p0);
        float a1 = (gt == 2) ? tanh_f(p1) : sigmoid_f(p1);
        sg[0][j] = a0;
        sg[1][j] = a1;
        __syncthreads();

        if (j < 256) {
            int r  = j >> 7;
            int kk = j & (HID - 1);
            float iv = sg[r][kk];
            float fv = sg[r][kk + 128];
            float gv = sg[r][kk + 256];
            float ov = sg[r][kk + 384];
            c = fmaf(fv, c, iv * gv);
            float hn = ov * tanh_f(c);
            sh[r][kk] = hn;
            if (layer == 0) {
                g_y1[((size_t)t * BATCH + b0 + r) * HID + kk] = hn;
            } else if (t == SEQ - 1) {
                out[(size_t)(b0 + r) * HID + kk] = hn;
            }
        }
        __syncthreads();
    }
}

// -------- launch --------
extern "C" void kernel_launch(void* const* d_in, const int* in_sizes, int n_in,
                              void* d_out, int out_size) {
    const float* x    = (const float*)d_in[0];
    const float* Wih0 = (const float*)d_in[1];
    const float* Whh0 = (const float*)d_in[2];
    const float* bih0 = (const float*)d_in[3];
    const float* bhh0 = (const float*)d_in[4];
    const float* Wih1 = (const float*)d_in[5];
    const float* Whh1 = (const float*)d_in[6];
    const float* bih1 = (const float*)d_in[7];
    const float* bhh1 = (const float*)d_in[8];
    float* out = (float*)d_out;

    // 1. x (B,S,C) -> (S,B,C)
    k_transpose<<<(SEQ * BATCH * CIN) / 256, 256>>>(x);
    // 2. xg = xT @ Wih0^T + bih0 + bhh0
    k_gemm<CIN, 0><<<dim3((SEQ * BATCH) / 128, GATES / 64), 256>>>(Wih0, bih0, bhh0);
    // 3. layer-0 recurrence -> g_y1
    k_recur<<<BATCH / 2, 512>>>(Whh0, nullptr, 0);
    // 4. xg = y1 @ Wih1^T + bih1 + bhh1
    k_gemm<HID, 1><<<dim3((SEQ * BATCH) / 128, GATES / 64), 256>>>(Wih1, bih1, bhh1);
    // 5. layer-1 recurrence -> out (last timestep only)
    k_recur<<<BATCH / 2, 512>>>(Whh1, out, 1);
}